// round 5
// baseline (speedup 1.0000x reference)
#include <cuda_runtime.h>
#include <cub/cub.cuh>

#define MAXN 1600000
#define MAXB 8
#define PRE_K 6000
#define POST_K 1000
#define MASKW 94            // ceil(6000/64)
#define NBINS 4096
#define CAP   6144          // per-image candidate buffer (= 1024 threads * 6 items)
#define NEGV  -1000000000.0f
#define NEG_HALF -500000000.0f

// ---------------- static device scratch (no allocations allowed) ----------------
__device__ float4             g_boxes[MAXN];
__device__ float              g_score[MAXN];
__device__ unsigned int       g_hist[MAXB * NBINS];
__device__ int                g_thresh[MAXB];
__device__ unsigned int       g_cnt[MAXB];
__device__ unsigned long long g_buf[(size_t)MAXB * CAP];
__device__ float4             g_cboxes[MAXB * PRE_K];
__device__ float              g_cscore[MAXB * PRE_K];
__device__ int                g_cidx[MAXB * PRE_K];
__device__ int                g_rowany[MAXB * PRE_K];
__device__ unsigned long long g_mask[(size_t)MAXB * PRE_K * MASKW]; // upper-tri only; bss zero
__device__ int                g_kept[MAXB * POST_K];

// ---------------- XLA-exact sigmoid: 0.5 + 0.5*tanh(0.5x), fast-tanh poly ------
__device__ __forceinline__ float xla_tanh(float x) {
    float ax = fabsf(x);
    float xc = fminf(fmaxf(x, -7.99881172180175781f), 7.99881172180175781f);
    float x2 = __fmul_rn(xc, xc);
    float p = fmaf(x2, -2.76076847742355e-16f, 2.00018790482477e-13f);
    p = fmaf(p, x2, -8.60467152213735e-11f);
    p = fmaf(p, x2,  5.12229709037114e-08f);
    p = fmaf(p, x2,  1.48572235717979e-05f);
    p = fmaf(p, x2,  6.37261928875436e-04f);
    p = fmaf(p, x2,  4.89352455891786e-03f);
    float num = __fmul_rn(xc, p);
    float q = fmaf(x2, 1.19825839466702e-06f, 1.18534705686654e-04f);
    q = fmaf(q, x2, 2.26843463243900e-03f);
    q = fmaf(q, x2, 4.89352518554385e-03f);
    float r = __fdiv_rn(num, q);
    return (ax < 0.0004f) ? x : r;
}
__device__ __forceinline__ float xla_sigmoid(float x) {
    float t = xla_tanh(__fmul_rn(0.5f, x));
    return __fadd_rn(__fmul_rn(0.5f, t), 0.5f);
}

__device__ __forceinline__ int score_bin(float s) {
    if (s <= 0.0f) return 0;                       // NEGV and exact zeros -> bin 0
    int b = (int)(__fmul_rn(s, (float)NBINS));
    return b > (NBINS - 1) ? (NBINS - 1) : b;
}
__device__ __forceinline__ unsigned score_key(float s) {  // ascending uint <-> ascending float
    unsigned ub = __float_as_uint(s);
    return (ub & 0x80000000u) ? ~ub : (ub | 0x80000000u);
}

// ---------------- kernel 0: zero histogram -------------------------------------
__global__ void k_zero(int B)
{
    int t = blockIdx.x * blockDim.x + threadIdx.x;
    if (t < B * NBINS) g_hist[t] = 0;
}

// ---------------- kernel 1: decode boxes, score, histogram ---------------------
__global__ __launch_bounds__(256)
void k_decode(const float4* __restrict__ anchors, const int* __restrict__ bidx,
              const int* __restrict__ sizes, const float* __restrict__ logits,
              const float4* __restrict__ deltas, int N)
{
    int i = blockIdx.x * blockDim.x + threadIdx.x;
    if (i >= N) return;
    float4 a = anchors[i];
    float4 d = deltas[i];
    int b = bidx[i];
    float H = (float)sizes[2 * b];
    float W = (float)sizes[2 * b + 1];

    // exact op order of reference, no FMA contraction
    float aw = __fsub_rn(a.z, a.x);
    float ah = __fsub_rn(a.w, a.y);
    float ax = __fadd_rn(a.x, __fmul_rn(0.5f, aw));
    float ay = __fadd_rn(a.y, __fmul_rn(0.5f, ah));
    float px = __fadd_rn(ax, __fmul_rn(d.x, aw));
    float py = __fadd_rn(ay, __fmul_rn(d.y, ah));
    float twc = fminf(fmaxf(d.z, -10.0f), 10.0f);
    float thc = fminf(fmaxf(d.w, -10.0f), 10.0f);
    float pw = __fmul_rn(aw, expf(twc));   // expf == libdevice __nv_expf == XLA exp
    float ph = __fmul_rn(ah, expf(thc));
    float x1 = __fsub_rn(px, __fmul_rn(0.5f, pw));
    float y1 = __fsub_rn(py, __fmul_rn(0.5f, ph));
    float x2 = __fadd_rn(px, __fmul_rn(0.5f, pw));
    float y2 = __fadd_rn(py, __fmul_rn(0.5f, ph));
    float Wm1 = __fsub_rn(W, 1.0f);
    float Hm1 = __fsub_rn(H, 1.0f);
    x1 = fminf(fmaxf(x1, 0.0f), Wm1);
    y1 = fminf(fmaxf(y1, 0.0f), Hm1);
    x2 = fminf(fmaxf(x2, 0.0f), Wm1);
    y2 = fminf(fmaxf(y2, 0.0f), Hm1);
    bool valid = (__fsub_rn(x2, x1) >= 16.0f) && (__fsub_rn(y2, y1) >= 16.0f);

    float fg = xla_sigmoid(logits[i]);
    float sc = valid ? fg : NEGV;

    g_boxes[i] = make_float4(x1, y1, x2, y2);
    g_score[i] = sc;
    atomicAdd(&g_hist[b * NBINS + score_bin(sc)], 1u);
}

// ---------------- kernel 2: per-image threshold bin ----------------------------
// 256 threads; thread t covers 16 bins in DESCENDING bin order.
__global__ __launch_bounds__(256)
void k_thresh()
{
    int b = blockIdx.x;
    int t = threadIdx.x;
    unsigned v[16]; unsigned s = 0;
    for (int k = 0; k < 16; k++) {
        v[k] = g_hist[b * NBINS + (NBINS - 1 - (t * 16 + k))];
        s += v[k];
    }
    __shared__ unsigned ps[256];
    ps[t] = s; __syncthreads();
    for (int off = 1; off < 256; off <<= 1) {
        unsigned x = (t >= off) ? ps[t - off] : 0u;
        __syncthreads();
        ps[t] += x;
        __syncthreads();
    }
    unsigned cum = ps[t] - s;        // exclusive prefix (descending order)
    for (int k = 0; k < 16; k++) {
        unsigned nc = cum + v[k];
        if (cum < PRE_K && nc >= PRE_K)
            g_thresh[b] = NBINS - 1 - (t * 16 + k);   // unique transition writer
        cum = nc;
    }
    if (t == 255 && cum < PRE_K) g_thresh[b] = 0;     // total < PRE_K: take all
    if (t == 0) g_cnt[b] = 0;
}

// ---------------- kernel 3: compact candidates above threshold -----------------
__global__ __launch_bounds__(256)
void k_compact(const int* __restrict__ bidx, int N)
{
    int i = blockIdx.x * blockDim.x + threadIdx.x;
    if (i >= N) return;
    int b = bidx[i];
    float s = g_score[i];
    if (score_bin(s) >= g_thresh[b]) {
        unsigned pos = atomicAdd(&g_cnt[b], 1u);
        if (pos < CAP) {
            unsigned long long key =
                ((unsigned long long)(~score_key(s)) << 21) | (unsigned)i;
            g_buf[(size_t)b * CAP + pos] = key;
        }
    }
}

// ---------------- kernel 4: per-image block sort of candidates -----------------
// key = inv(scoreKey)<<21 | gidx : ascending sort == (score desc, idx asc), stable
using BlockSortT = cub::BlockRadixSort<unsigned long long, 1024, 6>;

__global__ __launch_bounds__(1024)
void k_sortk()
{
    extern __shared__ char smem_raw[];
    BlockSortT::TempStorage& ts = *reinterpret_cast<BlockSortT::TempStorage*>(smem_raw);
    int b = blockIdx.x;
    unsigned cnt = g_cnt[b];
    if (cnt > CAP) cnt = CAP;
    unsigned long long keys[6];
    #pragma unroll
    for (int k = 0; k < 6; k++) {
        int p = threadIdx.x * 6 + k;
        keys[k] = (p < (int)cnt) ? g_buf[(size_t)b * CAP + p] : ~0ull;
    }
    BlockSortT(ts).Sort(keys, 0, 53);
    #pragma unroll
    for (int k = 0; k < 6; k++) {
        int p = threadIdx.x * 6 + k;
        if (p < PRE_K) {
            int o = b * PRE_K + p;
            g_rowany[o] = 0;
            unsigned long long key = keys[k];
            if (key >> 53) {             // padding sentinel
                g_cidx[o] = 0; g_cscore[o] = NEGV;
                g_cboxes[o] = make_float4(0, 0, 0, 0);
            } else {
                int gi = (int)(key & 0x1FFFFFu);
                g_cidx[o] = gi;
                g_cscore[o] = g_score[gi];
                g_cboxes[o] = g_boxes[gi];
            }
        }
    }
}

// ---------------- kernel 5: IoU suppression bitmask (upper triangle) -----------
__global__ __launch_bounds__(64)
void k_mask()
{
    int b = blockIdx.z, rb = blockIdx.y, cb = blockIdx.x;
    if (cb < rb) return;                       // lower triangle stays zero (bss)
    __shared__ float4 sbx[64];
    __shared__ float  sar[64];
    int t = threadIdx.x;
    int cbase = cb * 64;
    int ncol = min(64, PRE_K - cbase);
    if (t < ncol) {
        float4 v = g_cboxes[b * PRE_K + cbase + t];
        sbx[t] = v;
        sar[t] = __fmul_rn(__fsub_rn(v.z, v.x), __fsub_rn(v.w, v.y));
    }
    __syncthreads();
    int i = rb * 64 + t;
    if (i >= PRE_K) return;
    float4 bi_ = g_cboxes[b * PRE_K + i];
    float ai = __fmul_rn(__fsub_rn(bi_.z, bi_.x), __fsub_rn(bi_.w, bi_.y));
    unsigned long long bits = 0;
    for (int j = 0; j < ncol; j++) {
        float4 bj = sbx[j];
        float ix1 = fmaxf(bi_.x, bj.x), iy1 = fmaxf(bi_.y, bj.y);
        float ix2 = fminf(bi_.z, bj.z), iy2 = fminf(bi_.w, bj.w);
        float inter = __fmul_rn(fmaxf(__fsub_rn(ix2, ix1), 0.0f),
                                fmaxf(__fsub_rn(iy2, iy1), 0.0f));
        float denom = __fadd_rn(__fsub_rn(__fadd_rn(sar[j], ai), inter), 1e-9f);
        if (__fdiv_rn(inter, denom) > 0.7f) bits |= 1ull << j;
    }
    g_mask[((size_t)b * PRE_K + i) * MASKW + cb] = bits;
    unsigned long long nonself = bits;
    if (cb == rb) nonself &= ~(1ull << (i - cbase));
    if (nonself) g_rowany[b * PRE_K + i] = 1;   // benign race: all writers store 1
}

// ---------------- kernel 6: sequential greedy NMS (one warp per image) ---------
// removed-bitmask lives in shared; all lanes run the serial scan via broadcast LDS
__global__ __launch_bounds__(32)
void k_nms()
{
    int b = blockIdx.x;
    int lane = threadIdx.x;
    __shared__ float sscore[PRE_K];
    __shared__ unsigned long long srany[MASKW];
    __shared__ unsigned long long rem[MASKW];
    const int base = b * PRE_K;
    for (int i = lane; i < PRE_K; i += 32) sscore[i] = g_cscore[base + i];
    for (int w = lane; w < MASKW; w += 32) {
        unsigned long long bits = 0;
        int nrows = min(64, PRE_K - w * 64);
        for (int r = 0; r < nrows; r++)
            if (g_rowany[base + w * 64 + r]) bits |= 1ull << r;
        srany[w] = bits;
        rem[w] = 0ull;
    }
    __syncwarp();

    const unsigned long long* mrow = g_mask + (size_t)base * MASKW;
    const int outb = b * POST_K;
    int i = 0, nk = 0;
    while (i < PRE_K && nk < POST_K) {
        int w = i >> 6;
        if ((i & 63) == 0 && nk + 64 <= POST_K && i + 64 <= PRE_K &&
            srany[w] == 0ull && rem[w] == 0ull && sscore[i + 63] > NEG_HALF) {
            // fast path: all 64 survive, nothing suppressed, state unchanged
            g_kept[outb + nk + lane] = i + lane;
            g_kept[outb + nk + 32 + lane] = i + 32 + lane;
            nk += 64; i += 64; continue;
        }
        if (!((rem[w] >> (i & 63)) & 1ull)) {
            if (sscore[i] <= NEG_HALF) break;    // sorted: rest invalid
            if (lane == 0) g_kept[outb + nk] = i;
            nk++;
            if ((srany[w] >> (i & 63)) & 1ull) { // row suppresses someone: OR its mask
                const unsigned long long* m = mrow + (size_t)i * MASKW;
                rem[lane] |= m[lane];
                int w1 = lane + 32; if (w1 < MASKW) rem[w1] |= m[w1];
                int w2 = lane + 64; if (w2 < MASKW) rem[w2] |= m[w2];
                __syncwarp();
            }
        }
        i++;
    }
    for (int t = nk + lane; t < POST_K; t += 32) g_kept[outb + t] = -1;
}

// ---------------- kernel 7: write outputs --------------------------------------
__global__ __launch_bounds__(256)
void k_out(const float* __restrict__ logits, const float4* __restrict__ deltas,
           float* __restrict__ out, int B)
{
    int t = blockIdx.x * blockDim.x + threadIdx.x;
    int P = B * POST_K;
    if (t >= P) return;
    int b = t / POST_K;
    int j = g_kept[t];
    float4 pb = make_float4(0, 0, 0, 0), dl = make_float4(0, 0, 0, 0);
    float ob = 0.0f, bi = -1.0f, okf = 0.0f;
    if (j >= 0) {
        int gi = g_cidx[b * PRE_K + j];
        pb = g_cboxes[b * PRE_K + j];
        ob = logits[gi];
        dl = deltas[gi];
        bi = (float)b;
        okf = 1.0f;
    }
    // layout: props[4P] | bidx[P] | obj[P] | deltas[4P] | keep_ok[P]
    ((float4*)out)[t] = pb;
    out[4 * P + t] = bi;
    out[5 * P + t] = ob;
    ((float4*)(out + 6 * P))[t] = dl;
    out[10 * P + t] = okf;
}

// ---------------- launcher ------------------------------------------------------
extern "C" void kernel_launch(void* const* d_in, const int* in_sizes, int n_in,
                              void* d_out, int out_size)
{
    const float4* anchors = (const float4*)d_in[0];
    const int*    bidx    = (const int*)d_in[1];
    const int*    sizes   = (const int*)d_in[2];
    const float*  logits  = (const float*)d_in[3];
    const float4* deltas  = (const float4*)d_in[4];
    float* out = (float*)d_out;

    int N = in_sizes[0] / 4;
    int B = in_sizes[2] / 2;
    if (N > MAXN) N = MAXN;
    if (B > MAXB) B = MAXB;

    static bool attr_done = false;
    if (!attr_done) {
        cudaFuncSetAttribute(k_sortk, cudaFuncAttributeMaxDynamicSharedMemorySize,
                             (int)sizeof(BlockSortT::TempStorage));
        attr_done = true;
    }

    k_zero<<<(B * NBINS + 255) / 256, 256>>>(B);
    k_decode<<<(N + 255) / 256, 256>>>(anchors, bidx, sizes, logits, deltas, N);
    k_thresh<<<B, 256>>>();
    k_compact<<<(N + 255) / 256, 256>>>(bidx, N);
    k_sortk<<<B, 1024, sizeof(BlockSortT::TempStorage)>>>();
    dim3 mg(MASKW, MASKW, B);
    k_mask<<<mg, 64>>>();
    k_nms<<<B, 32>>>();
    k_out<<<(B * POST_K + 255) / 256, 256>>>(logits, deltas, out, B);
}